// round 7
// baseline (speedup 1.0000x reference)
#include <cuda_runtime.h>
#include <cuda_bf16.h>
#include <math.h>

#define NN 50000
#define NE 800000
#define HD 128
#define NG 64
#define POOL_SPLIT 16

// ---------------- scratch (device globals; no runtime allocation) ----------------
// Vector-accessed buffers are float4 so the linker guarantees 16B alignment.
__device__ int   g_rowptr[NN + 1];
__device__ int   g_fillptr[NN];
__device__ int   g_csr_src[NE];
__device__ float g_csr_w[NE];

__device__ float4 g_support[NN * 32];   // [NN, 128] viewed as [NN, 32] float4
__device__ float4 g_G1[NN * 32];
__device__ float4 g_G2[NN * 32];
__device__ float4 g_G3[NN * 32];

__device__ float g_ssup[NN];
__device__ float g_score[NN];

__device__ int   g_gcount[NG];
__device__ int   g_gstart[NG + 1];

__device__ float g_psum[NG * 3 * POOL_SPLIT * HD];
__device__ float g_pmax[NG * 3 * POOL_SPLIT * HD];
__device__ float g_pooled[NG * 768];   // [avg(384) | max(384)] per graph

__device__ __forceinline__ int clampi(int v, int lo, int hi) {
    return v < lo ? lo : (v > hi ? hi : v);
}

// ---------------- CSR build (edge_index is int32: [2, NE] row-major) -------------
__global__ void k_zero() {
    int i = blockIdx.x * blockDim.x + threadIdx.x;
    if (i < NN) g_fillptr[i] = 0;
    if (i < NG) g_gcount[i] = 0;
}

__global__ void k_hist(const int* __restrict__ ei) {
    int i = blockIdx.x * blockDim.x + threadIdx.x;
    if (i < NE) {
        int d = clampi(ei[NE + i], 0, NN - 1);
        atomicAdd(&g_fillptr[d], 1);
    }
}

// single-block exclusive scan over g_fillptr (deg) -> g_rowptr, copy into g_fillptr
__global__ void k_scan() {
    __shared__ int sdata[1024];
    __shared__ int s_off;
    int tid = threadIdx.x;
    if (tid == 0) s_off = 0;
    __syncthreads();
    for (int base = 0; base < NN; base += 1024) {
        int i = base + tid;
        int v = (i < NN) ? g_fillptr[i] : 0;
        sdata[tid] = v;
        __syncthreads();
        for (int off = 1; off < 1024; off <<= 1) {
            int t = (tid >= off) ? sdata[tid - off] : 0;
            __syncthreads();
            sdata[tid] += t;
            __syncthreads();
        }
        int excl = sdata[tid] - v + s_off;
        if (i < NN) { g_rowptr[i] = excl; g_fillptr[i] = excl; }
        __syncthreads();
        if (tid == 0) s_off += sdata[1023];
        __syncthreads();
    }
    if (threadIdx.x == 0) g_rowptr[NN] = s_off;
}

__global__ void k_fill(const int* __restrict__ ei,
                       const float* __restrict__ ew) {
    int i = blockIdx.x * blockDim.x + threadIdx.x;
    if (i < NE) {
        int s = clampi(ei[i], 0, NN - 1);
        int d = clampi(ei[NE + i], 0, NN - 1);
        int pos = atomicAdd(&g_fillptr[d], 1);
        if (pos < NE) {
            g_csr_src[pos] = s;
            g_csr_w[pos]   = ew[i];
        }
    }
}

// ---------------- dense GEMM: g_support = X @ W  (X chosen by sel) ---------------
__global__ void k_gemm(const float* __restrict__ Xext,
                       const float* __restrict__ W, int sel) {
    __shared__ float xs[32 * HD];           // 16 KB
    const float* X = (sel == 0) ? Xext
                   : (sel == 1) ? (const float*)g_G1
                                : (const float*)g_G2;
    int n0 = blockIdx.x * 32;
    int t = threadIdx.x;

    int nvalid = NN - n0; if (nvalid > 32) nvalid = 32;
    for (int i = t; i < 32 * HD; i += 512) {
        int nl = i >> 7;
        xs[i] = (nl < nvalid) ? X[n0 * HD + i] : 0.0f;
    }
    __syncthreads();

    int rp = t >> 5;          // 0..15 (row pair)
    int j4 = t & 31;          // float4 column group
    const float4* W4 = (const float4*)W;
    const float* xa_row = &xs[(2 * rp) * HD];
    const float* xb_row = &xs[(2 * rp + 1) * HD];

    float4 accA = make_float4(0.f, 0.f, 0.f, 0.f);
    float4 accB = make_float4(0.f, 0.f, 0.f, 0.f);

#pragma unroll 8
    for (int k = 0; k < HD; k++) {
        float4 w = __ldg(&W4[k * 32 + j4]);
        float xa = xa_row[k];
        float xb = xb_row[k];
        accA.x += xa * w.x; accA.y += xa * w.y; accA.z += xa * w.z; accA.w += xa * w.w;
        accB.x += xb * w.x; accB.y += xb * w.y; accB.z += xb * w.z; accB.w += xb * w.w;
    }

    int na = n0 + 2 * rp, nb = na + 1;
    if (na < NN) g_support[na * 32 + j4] = accA;
    if (nb < NN) g_support[nb * 32 + j4] = accB;
}

// ---------------- SpMM gather: out = relu(b + sum_e w_e * support[src_e]) --------
__global__ void k_spmm(const float* __restrict__ bias, int sel) {
    int gt = blockIdx.x * blockDim.x + threadIdx.x;
    int n = gt >> 5;
    int lane = gt & 31;
    if (n >= NN) return;

    float4* out = (sel == 1) ? g_G1 : (sel == 2) ? g_G2 : g_G3;
    int beg = g_rowptr[n], end = g_rowptr[n + 1];
    float4 acc = make_float4(0.f, 0.f, 0.f, 0.f);

    for (int e = beg; e < end; e++) {
        int s = g_csr_src[e];
        float w = g_csr_w[e];
        float4 v = __ldg(&g_support[s * 32 + lane]);
        acc.x += w * v.x; acc.y += w * v.y; acc.z += w * v.z; acc.w += w * v.w;
    }

    float4 b = ((const float4*)bias)[lane];
    float4 r;
    r.x = fmaxf(acc.x + b.x, 0.f);
    r.y = fmaxf(acc.y + b.y, 0.f);
    r.z = fmaxf(acc.z + b.z, 0.f);
    r.w = fmaxf(acc.w + b.w, 0.f);
    out[n * 32 + lane] = r;
}

// ---------------- attention score support: ssup[n] = h[n,:] . wa ----------------
__global__ void k_ssup(const float* __restrict__ wa) {
    int gt = blockIdx.x * blockDim.x + threadIdx.x;
    int n = gt >> 5;
    int lane = gt & 31;
    if (n >= NN) return;

    float acc = 0.f;
    const float* H0 = (const float*)g_G1;
    const float* H1 = (const float*)g_G2;
    const float* H2 = (const float*)g_G3;
    const float* H[3] = { H0, H1, H2 };
#pragma unroll
    for (int r = 0; r < 3; r++) {
        const float* h = H[r] + n * HD;
        const float* w = wa + r * HD;
#pragma unroll
        for (int d = lane; d < HD; d += 32) acc += h[d] * w[d];
    }
#pragma unroll
    for (int o = 16; o > 0; o >>= 1) acc += __shfl_down_sync(0xffffffffu, acc, o);
    if (lane == 0) g_ssup[n] = acc;
}

__global__ void k_score(const float* __restrict__ ba) {
    int n = blockIdx.x * blockDim.x + threadIdx.x;
    if (n >= NN) return;
    int beg = g_rowptr[n], end = g_rowptr[n + 1];
    float acc = 0.f;
    for (int e = beg; e < end; e++)
        acc += g_csr_w[e] * __ldg(&g_ssup[g_csr_src[e]]);
    g_score[n] = tanhf(acc + ba[0]);
}

// ---------------- per-graph ranges (graph_indicator is int32) ----------------
__global__ void k_ghist(const int* __restrict__ gi) {
    int i = blockIdx.x * blockDim.x + threadIdx.x;
    if (i < NN) atomicAdd(&g_gcount[clampi(gi[i], 0, NG - 1)], 1);
}

__global__ void k_gscan() {
    g_gstart[0] = 0;
    for (int g = 0; g < NG; g++) g_gstart[g + 1] = g_gstart[g] + g_gcount[g];
}

// ---------------- pooling: avg + max of h*score per graph ----------------
__global__ void k_pool() {
    int bx = blockIdx.x;                 // (g, c, s)
    int g = bx / (3 * POOL_SPLIT);
    int c = (bx / POOL_SPLIT) % 3;
    int s = bx % POOL_SPLIT;
    int t = threadIdx.x;                 // dim within chunk

    int gs = g_gstart[g], ge = g_gstart[g + 1];
    const float* H = (c == 0) ? (const float*)g_G1
                   : (c == 1) ? (const float*)g_G2
                              : (const float*)g_G3;

    float sum = 0.f, mx = -INFINITY;
    for (int n = gs + s; n < ge; n += POOL_SPLIT) {
        float v = H[n * HD + t] * g_score[n];
        sum += v;
        mx = fmaxf(mx, v);
    }
    int idx = ((g * 3 + c) * POOL_SPLIT + s) * HD + t;
    g_psum[idx] = sum;
    g_pmax[idx] = mx;
}

__global__ void k_pool_reduce() {
    int bx = blockIdx.x;                 // (g, c)
    int g = bx / 3, c = bx % 3;
    int t = threadIdx.x;

    float sum = 0.f, mx = -INFINITY;
#pragma unroll
    for (int s = 0; s < POOL_SPLIT; s++) {
        int idx = ((g * 3 + c) * POOL_SPLIT + s) * HD + t;
        sum += g_psum[idx];
        mx = fmaxf(mx, g_pmax[idx]);
    }
    int cnt = g_gstart[g + 1] - g_gstart[g];
    float denom = (float)(cnt > 1 ? cnt : 1);
    int j = c * HD + t;
    g_pooled[g * 768 + j]       = sum / denom;
    g_pooled[g * 768 + 384 + j] = mx;
}

// ---------------- final: out[g] = relu(pooled[g] @ Wf + bf) ----------------
__global__ void k_final(const float* __restrict__ Wf,
                        const float* __restrict__ bf,
                        float* __restrict__ out) {
    int g = blockIdx.x;
    int t = threadIdx.x;
    const float* p = &g_pooled[g * 768];
    float acc = bf[t];
#pragma unroll 8
    for (int k = 0; k < 768; k++)
        acc += p[k] * __ldg(&Wf[k * HD + t]);
    out[g * HD + t] = fmaxf(acc, 0.f);
}

// ---------------- launch (pure kernel launches; graph-capturable) ----------------
extern "C" void kernel_launch(void* const* d_in, const int* in_sizes, int n_in,
                              void* d_out, int out_size) {
    const int*   edge_index = (const int*)d_in[0];     // int32 [2, NE]
    const float* edge_w     = (const float*)d_in[1];
    const float* x_in       = (const float*)d_in[2];
    const int*   gind       = (const int*)d_in[3];     // int32 [NN]
    const float* W1 = (const float*)d_in[4];
    const float* b1 = (const float*)d_in[5];
    const float* W2 = (const float*)d_in[6];
    const float* b2 = (const float*)d_in[7];
    const float* W3 = (const float*)d_in[8];
    const float* b3 = (const float*)d_in[9];
    const float* wa = (const float*)d_in[10];
    const float* ba = (const float*)d_in[11];
    const float* Wf = (const float*)d_in[12];
    const float* bf = (const float*)d_in[13];
    float* out = (float*)d_out;

    // CSR build
    k_zero<<<(NN + 255) / 256, 256>>>();
    k_hist<<<(NE + 255) / 256, 256>>>(edge_index);
    k_scan<<<1, 1024>>>();
    k_fill<<<(NE + 255) / 256, 256>>>(edge_index, edge_w);
    k_ghist<<<(NN + 255) / 256, 256>>>(gind);
    k_gscan<<<1, 1>>>();

    const int gemm_grid = (NN + 31) / 32;
    const int spmm_grid = (NN * 32 + 255) / 256;   // exactly NN warps

    // layer 1
    k_gemm<<<gemm_grid, 512>>>(x_in, W1, 0);
    k_spmm<<<spmm_grid, 256>>>(b1, 1);
    // layer 2
    k_gemm<<<gemm_grid, 512>>>(x_in, W2, 1);
    k_spmm<<<spmm_grid, 256>>>(b2, 2);
    // layer 3
    k_gemm<<<gemm_grid, 512>>>(x_in, W3, 2);
    k_spmm<<<spmm_grid, 256>>>(b3, 3);

    // attention score
    k_ssup<<<spmm_grid, 256>>>(wa);
    k_score<<<(NN + 255) / 256, 256>>>(ba);

    // pooling
    k_pool<<<NG * 3 * POOL_SPLIT, HD>>>();
    k_pool_reduce<<<NG * 3, HD>>>();

    // output head
    k_final<<<NG, HD>>>(Wf, bf, out);
}